// round 1
// baseline (speedup 1.0000x reference)
#include <cuda_runtime.h>
#include <math.h>

#define HIDDEN 256
#define TM 64
#define MPAD 260            // padded activation row stride (floats); 16B-aligned rows
#define NTHR 256
#define PIX_PER_BATCH (128*128)
#define TOTAL_PIX (16*PIX_PER_BATCH)
#define OUT_PIX (TOTAL_PIX*3)

// dynamic smem layout (floats):
//   bufA   [TM][MPAD]      = 16640
//   bufB   [TM][MPAD]      = 16640
//   Ws     [16][HIDDEN]    = 4096
//   coords [2][TM]         = 128
#define SMEM_FLOATS (TM*MPAD*2 + 16*HIDDEN + 2*TM)
#define SMEM_BYTES  (SMEM_FLOATS*4)

// One 256->256 dense layer with ReLU for a 64-pixel tile.
// in_s/out_s: [TM][MPAD] activation buffers. Ws: 16xHIDDEN staging tile.
// Thread (tx,ty): tx in [0,32) owns outputs n0=tx*8..+7; ty in [0,8) owns pixels m0=ty*8..+7.
__device__ __forceinline__ void dense256(
    const float* __restrict__ W, const float* __restrict__ bias,
    const float* in_s, float* out_s, float* Ws,
    int tid, int tx, int ty)
{
    float acc[8][8];
#pragma unroll
    for (int i = 0; i < 8; i++)
#pragma unroll
        for (int j = 0; j < 8; j++) acc[i][j] = 0.f;

    const int m0 = ty * 8, n0 = tx * 8;

    for (int k0 = 0; k0 < HIDDEN; k0 += 16) {
        __syncthreads();   // protect Ws from previous iter's readers (also post-producer barrier at k0=0)
        // stage W[k0:k0+16, :] -> Ws (4096 floats, 16/thread via float4)
        const float4* Wg = reinterpret_cast<const float4*>(W + k0 * HIDDEN);
        float4* Wsv = reinterpret_cast<float4*>(Ws);
#pragma unroll
        for (int i = 0; i < 4; i++) Wsv[tid + i * NTHR] = Wg[tid + i * NTHR];
        __syncthreads();

#pragma unroll
        for (int kk = 0; kk < 16; kk++) {
            float a[8];
#pragma unroll
            for (int i = 0; i < 8; i++) a[i] = in_s[(m0 + i) * MPAD + k0 + kk];  // warp-broadcast
            float4 w0 = *reinterpret_cast<const float4*>(&Ws[kk * HIDDEN + n0]);
            float4 w1 = *reinterpret_cast<const float4*>(&Ws[kk * HIDDEN + n0 + 4]);
            float w[8] = {w0.x, w0.y, w0.z, w0.w, w1.x, w1.y, w1.z, w1.w};
#pragma unroll
            for (int i = 0; i < 8; i++)
#pragma unroll
                for (int j = 0; j < 8; j++)
                    acc[i][j] = fmaf(a[i], w[j], acc[i][j]);
        }
    }

    // epilogue: bias + ReLU, store 8x8 tile (2x float4 per pixel row)
    float bb[8];
#pragma unroll
    for (int j = 0; j < 8; j++) bb[j] = bias[n0 + j];
#pragma unroll
    for (int i = 0; i < 8; i++) {
        float v[8];
#pragma unroll
        for (int j = 0; j < 8; j++) v[j] = fmaxf(acc[i][j] + bb[j], 0.f);
        *reinterpret_cast<float4*>(&out_s[(m0 + i) * MPAD + n0]) =
            make_float4(v[0], v[1], v[2], v[3]);
        *reinterpret_cast<float4*>(&out_s[(m0 + i) * MPAD + n0 + 4]) =
            make_float4(v[4], v[5], v[6], v[7]);
    }
}

__global__ void __launch_bounds__(NTHR, 1) inr_fused_kernel(
    const float* __restrict__ x,            // (B,H,W,2)
    const int*   __restrict__ sample_idx,   // (B,)
    const float* __restrict__ shiftv,       // (16,2) [dy,dx]
    const float* __restrict__ rotang,       // (16,1)
    const float* __restrict__ cscales,      // (16,3)
    const float* __restrict__ cshifts,      // (16,3)
    const float* __restrict__ W1, const float* __restrict__ b1,   // (2,256),(256)
    const float* __restrict__ W2, const float* __restrict__ b2,   // (256,256),(256)
    const float* __restrict__ W3, const float* __restrict__ b3,   // (256,256),(256)
    const float* __restrict__ W4, const float* __restrict__ b4,   // (256,3),(3)
    float* __restrict__ out)                // 786432 (+16 dx)(+16 dy)
{
    extern __shared__ float smem[];
    float* bufA   = smem;
    float* bufB   = bufA + TM * MPAD;
    float* Ws     = bufB + TM * MPAD;
    float* coords = Ws + 16 * HIDDEN;       // [2][TM]

    const int tid = threadIdx.x;
    const int tx = tid & 31, ty = tid >> 5;
    const int p0 = blockIdx.x * TM;         // blocks are batch-aligned (16384 px / batch)
    const int b  = p0 / PIX_PER_BATCH;

    const int   sidx = sample_idx[b];
    const float dyv  = shiftv[sidx * 2 + 0];
    const float dxv  = shiftv[sidx * 2 + 1];
    const float ang  = rotang[sidx];
    float sv, cv;
    sincosf(ang, &sv, &cv);

    // per-pixel rotated+shifted coords
    if (tid < TM) {
        float2 xv = reinterpret_cast<const float2*>(x)[p0 + tid];
        coords[tid]      = cv * xv.x - sv * xv.y + dxv;   // coord 0
        coords[TM + tid] = sv * xv.x + cv * xv.y + dyv;   // coord 1
    }
    __syncthreads();

    // layer 1: 2 -> 256, ReLU, into bufA
    {
        const int m0 = ty * 8, n0 = tx * 8;
        float wa[8], wb[8], bb[8];
#pragma unroll
        for (int j = 0; j < 8; j++) {
            wa[j] = W1[n0 + j];
            wb[j] = W1[HIDDEN + n0 + j];
            bb[j] = b1[n0 + j];
        }
#pragma unroll
        for (int i = 0; i < 8; i++) {
            float c0 = coords[m0 + i];
            float c1 = coords[TM + m0 + i];
            float v[8];
#pragma unroll
            for (int j = 0; j < 8; j++) {
                float t = fmaf(c1, wb[j], bb[j]);
                t = fmaf(c0, wa[j], t);
                v[j] = fmaxf(t, 0.f);
            }
            *reinterpret_cast<float4*>(&bufA[(m0 + i) * MPAD + n0]) =
                make_float4(v[0], v[1], v[2], v[3]);
            *reinterpret_cast<float4*>(&bufA[(m0 + i) * MPAD + n0 + 4]) =
                make_float4(v[4], v[5], v[6], v[7]);
        }
    }
    // dense256 opens with __syncthreads(), which orders the bufA writes above

    dense256(W2, b2, bufA, bufB, Ws, tid, tx, ty);   // layer 2: bufA -> bufB
    dense256(W3, b3, bufB, bufA, Ws, tid, tx, ty);   // layer 3: bufB -> bufA
    __syncthreads();

    // layer 4: 256 -> 3, plus per-sample color affine
    if (tid < TM * 3) {
        const int m = tid / 3, j = tid - 3 * m;
        const float* hrow = &bufA[m * MPAD];
        float s = 0.f;
#pragma unroll 8
        for (int k = 0; k < HIDDEN; k++)
            s = fmaf(hrow[k], W4[k * 3 + j], s);     // W4 is 3KB: L1-resident
        s += b4[j];
        if (sidx != 0)
            s = fmaf(s, cscales[sidx * 3 + j], cshifts[sidx * 3 + j]);
        out[(p0 + m) * 3 + j] = s;
    }

    // dx / dy passthrough outputs (one writer per batch)
    if ((blockIdx.x & 255) == 0 && tid == 0) {
        out[OUT_PIX + b]      = dxv;   // dx = shift[:,1]
        out[OUT_PIX + 16 + b] = dyv;   // dy = shift[:,0]
    }
}

extern "C" void kernel_launch(void* const* d_in, const int* in_sizes, int n_in,
                              void* d_out, int out_size)
{
    (void)in_sizes; (void)n_in; (void)out_size;
    const float* x      = (const float*)d_in[0];
    const int*   sidx   = (const int*)  d_in[1];
    const float* shiftv = (const float*)d_in[2];
    const float* rotang = (const float*)d_in[3];
    const float* cscal  = (const float*)d_in[4];
    const float* cshft  = (const float*)d_in[5];
    const float* W1 = (const float*)d_in[6];
    const float* b1 = (const float*)d_in[7];
    const float* W2 = (const float*)d_in[8];
    const float* b2 = (const float*)d_in[9];
    const float* W3 = (const float*)d_in[10];
    const float* b3 = (const float*)d_in[11];
    const float* W4 = (const float*)d_in[12];
    const float* b4 = (const float*)d_in[13];
    float* out = (float*)d_out;

    cudaFuncSetAttribute(inr_fused_kernel,
                         cudaFuncAttributeMaxDynamicSharedMemorySize, SMEM_BYTES);

    inr_fused_kernel<<<TOTAL_PIX / TM, NTHR, SMEM_BYTES>>>(
        x, sidx, shiftv, rotang, cscal, cshft,
        W1, b1, W2, b2, W3, b3, W4, b4, out);
}